// round 2
// baseline (speedup 1.0000x reference)
#include <cuda_runtime.h>
#include <math.h>

// Problem constants
namespace {
constexpr int B = 64, T = 256, E = 512, H = 512, TAGS = 50;
constexpr int G = 4 * H;   // 2048 (gate dim)
constexpr int M = T * B;   // 16384 rows
constexpr int NBLK_PER_DIR = 64;   // persistent blocks per direction
}

// Scratch (static device arrays — no cudaMalloc allowed)
__device__ float g_xs[M * E];        //  32 MB  embedded inputs [T*B, E]
__device__ float g_pre_f[M * G];     // 128 MB  x@Wih^T + biases (fwd)
__device__ float g_pre_b[M * G];     // 128 MB  (bwd)
__device__ float g_out1[M * 2 * H];  //  64 MB  layer-1 output [T*B, 2H]
__device__ float g_out2[M * 2 * H];  //  64 MB  layer-2 output
__device__ float g_hT[2][2][H * B];  // h double buffer, TRANSPOSED [parity][dir][j][b]
__device__ unsigned g_barcnt[2];               // per-dir barrier arrival counter
__device__ volatile unsigned g_bargen[2];      // per-dir barrier generation

// ---------------------------------------------------------------------------
__global__ void init_layer_kernel() {
  int i = blockIdx.x * blockDim.x + threadIdx.x;
  float* ht = &g_hT[0][0][0];
  if (i < 2 * 2 * H * B) ht[i] = 0.f;
  if (i < 2) { g_barcnt[i] = 0; g_bargen[i] = 0; }
}

// Embedding gather: g_xs[(t*B+b)*E + :] = emb[x[b,t], :]
__global__ void embed_kernel(const int* __restrict__ x,
                             const float* __restrict__ emb) {
  int row = blockIdx.x;        // t*B + b
  int t = row >> 6;
  int b = row & 63;
  int tok = x[b * T + t];
  const float4* src = reinterpret_cast<const float4*>(emb + (size_t)tok * E);
  float4* dst = reinterpret_cast<float4*>(g_xs + (size_t)row * E);
  dst[threadIdx.x] = src[threadIdx.x];   // 128 threads * float4 = 512 floats
}

// ---------------------------------------------------------------------------
// C[M, 2048] = A[M, K] @ W[2048, K]^T + (b1 + b2)
template <int K>
__global__ __launch_bounds__(256)
void sgemm_bias_kernel(const float* __restrict__ A,
                       const float* __restrict__ W,
                       const float* __restrict__ b1,
                       const float* __restrict__ b2,
                       float* __restrict__ C) {
  __shared__ float As[8][132];
  __shared__ float Ws[8][132];
  const int bm = blockIdx.y << 7;
  const int bn = blockIdx.x << 7;
  const int tid = threadIdx.x;
  const int tm = (tid >> 4) << 3;
  const int tn = (tid & 15) << 3;
  const int lrow = tid >> 1;
  const int lc4 = (tid & 1) << 2;
  const float* Ap = A + (size_t)(bm + lrow) * K + lc4;
  const float* Wp = W + (size_t)(bn + lrow) * K + lc4;

  float acc[8][8];
#pragma unroll
  for (int i = 0; i < 8; i++)
#pragma unroll
    for (int j = 0; j < 8; j++) acc[i][j] = 0.f;

  float4 av = *reinterpret_cast<const float4*>(Ap);
  float4 wv = *reinterpret_cast<const float4*>(Wp);

  for (int k0 = 0; k0 < K; k0 += 8) {
    __syncthreads();
    As[lc4 + 0][lrow] = av.x; As[lc4 + 1][lrow] = av.y;
    As[lc4 + 2][lrow] = av.z; As[lc4 + 3][lrow] = av.w;
    Ws[lc4 + 0][lrow] = wv.x; Ws[lc4 + 1][lrow] = wv.y;
    Ws[lc4 + 2][lrow] = wv.z; Ws[lc4 + 3][lrow] = wv.w;
    __syncthreads();
    if (k0 + 8 < K) {
      av = *reinterpret_cast<const float4*>(Ap + k0 + 8);
      wv = *reinterpret_cast<const float4*>(Wp + k0 + 8);
    }
#pragma unroll
    for (int kk = 0; kk < 8; kk++) {
      float ra[8], rw[8];
      *reinterpret_cast<float4*>(&ra[0]) = *reinterpret_cast<const float4*>(&As[kk][tm]);
      *reinterpret_cast<float4*>(&ra[4]) = *reinterpret_cast<const float4*>(&As[kk][tm + 4]);
      *reinterpret_cast<float4*>(&rw[0]) = *reinterpret_cast<const float4*>(&Ws[kk][tn]);
      *reinterpret_cast<float4*>(&rw[4]) = *reinterpret_cast<const float4*>(&Ws[kk][tn + 4]);
#pragma unroll
      for (int i = 0; i < 8; i++)
#pragma unroll
        for (int j = 0; j < 8; j++) acc[i][j] = fmaf(ra[i], rw[j], acc[i][j]);
    }
  }

  float bb[8];
#pragma unroll
  for (int j = 0; j < 8; j++) {
    int col = bn + tn + j;
    bb[j] = b1[col] + b2[col];
  }
#pragma unroll
  for (int i = 0; i < 8; i++) {
    size_t crow = (size_t)(bm + tm + i) * G + (bn + tn);
    float4 v0 = make_float4(acc[i][0] + bb[0], acc[i][1] + bb[1],
                            acc[i][2] + bb[2], acc[i][3] + bb[3]);
    float4 v1 = make_float4(acc[i][4] + bb[4], acc[i][5] + bb[5],
                            acc[i][6] + bb[6], acc[i][7] + bb[7]);
    *reinterpret_cast<float4*>(&C[crow]) = v0;
    *reinterpret_cast<float4*>(&C[crow + 4]) = v1;
  }
}

// ---------------------------------------------------------------------------
__device__ __forceinline__ float sigf(float x) {
  return 1.f / (1.f + __expf(-x));
}

// Persistent BiLSTM recurrence for one layer.
// Grid: 128 blocks (dir = bx>>6, j-tile = bx&63 covering 8 hidden units).
// 256 threads: jj = tid>>5 (8 hidden units), bc = tid&31 (32 batch pairs).
// Whh slice (32 rows x 512 k = 64KB) staged ONCE into smem, transposed to
// [k][jj*4 + gate] so the inner loop is one broadcast LDS.128 + one
// coalesced LDG.64 (.cg, L2-coherent) + 8 FFMA per k.
// c-state lives in registers. h double-buffered, transposed [j][b] in global.
__global__ __launch_bounds__(256, 1)
void lstm_persistent(const float* __restrict__ pre_f,
                     const float* __restrict__ pre_b,
                     const float* __restrict__ Whh_f,
                     const float* __restrict__ Whh_b,
                     float* __restrict__ out) {
  extern __shared__ float w_s[];   // [512][32]  = 64KB
  const int dir = blockIdx.x >> 6;
  const int jt = blockIdx.x & 63;
  const int j0 = jt << 3;
  const int tid = threadIdx.x;
  const int jj = tid >> 5;     // 0..7
  const int bc = tid & 31;     // 0..31 -> batches 2bc, 2bc+1
  const float* Whh = dir ? Whh_b : Whh_f;
  const float* pre = dir ? pre_b : pre_f;

  // Stage weight slice, transposed: w_s[k*32 + jl*4 + g] = Whh[g*512+j0+jl][k]
  for (int e = tid; e < 32 * 128; e += 256) {
    int rl = e >> 7;                 // 0..31 local row
    int k4 = (e & 127) << 2;
    int g = rl >> 3, jl = rl & 7;
    float4 v = *reinterpret_cast<const float4*>(
        &Whh[((size_t)(g * 512 + j0 + jl)) * 512 + k4]);
    w_s[(k4 + 0) * 32 + jl * 4 + g] = v.x;
    w_s[(k4 + 1) * 32 + jl * 4 + g] = v.y;
    w_s[(k4 + 2) * 32 + jl * 4 + g] = v.z;
    w_s[(k4 + 3) * 32 + jl * 4 + g] = v.w;
  }
  __syncthreads();

  const int j = j0 + jj;
  float c0 = 0.f, c1 = 0.f;

  for (int t = 0; t < T; t++) {
    const int tt = dir ? (T - 1 - t) : t;
    const float* hp = g_hT[t & 1][dir];
    float* hn = g_hT[(t & 1) ^ 1][dir];

    float acc[8];
#pragma unroll
    for (int i = 0; i < 8; i++) acc[i] = 0.f;

    const float* hpp = hp + (bc << 1);
    const float* wsp = w_s + (jj << 2);
#pragma unroll 8
    for (int k = 0; k < 512; k++) {
      float4 w = *reinterpret_cast<const float4*>(wsp + k * 32);
      float2 h = __ldcg(reinterpret_cast<const float2*>(hpp + k * 64));
      acc[0] = fmaf(w.x, h.x, acc[0]); acc[1] = fmaf(w.x, h.y, acc[1]);
      acc[2] = fmaf(w.y, h.x, acc[2]); acc[3] = fmaf(w.y, h.y, acc[3]);
      acc[4] = fmaf(w.z, h.x, acc[4]); acc[5] = fmaf(w.z, h.y, acc[5]);
      acc[6] = fmaf(w.w, h.x, acc[6]); acc[7] = fmaf(w.w, h.y, acc[7]);
    }

    // Epilogue: gates -> c, h for the two batches (2bc, 2bc+1)
    const int b0 = bc << 1;
    size_t pb = ((size_t)tt * 64 + b0) * 2048 + j;
    float gi0 = acc[0] + pre[pb];
    float gf0 = acc[2] + pre[pb + 512];
    float gg0 = acc[4] + pre[pb + 1024];
    float go0 = acc[6] + pre[pb + 1536];
    float gi1 = acc[1] + pre[pb + 2048];
    float gf1 = acc[3] + pre[pb + 2048 + 512];
    float gg1 = acc[5] + pre[pb + 2048 + 1024];
    float go1 = acc[7] + pre[pb + 2048 + 1536];

    c0 = sigf(gf0) * c0 + sigf(gi0) * tanhf(gg0);
    c1 = sigf(gf1) * c1 + sigf(gi1) * tanhf(gg1);
    float h0 = sigf(go0) * tanhf(c0);
    float h1 = sigf(go1) * tanhf(c1);

    *reinterpret_cast<float2*>(&hn[j * 64 + b0]) = make_float2(h0, h1);
    size_t ob = ((size_t)tt * 64 + b0) * 1024 + dir * 512 + j;
    out[ob] = h0;
    out[ob + 1024] = h1;

    // Grid barrier (per direction, 64 blocks) before next step reads hn.
    if (t != T - 1) {
      __threadfence();
      __syncthreads();
      if (tid == 0) {
        unsigned target = (unsigned)(t + 1);
        if (atomicAdd(&g_barcnt[dir], 1u) == NBLK_PER_DIR - 1) {
          g_barcnt[dir] = 0;
          __threadfence();
          atomicExch((unsigned*)&g_bargen[dir], target);
        } else {
          while (g_bargen[dir] < target) __nanosleep(64);
        }
      }
      __syncthreads();
    }
  }
}

// ---------------------------------------------------------------------------
// logits[b, t, tag] = out2[t*B+b, :] . fcW[tag, :] + fcb[tag]
__global__ __launch_bounds__(256)
void fc_kernel(const float* __restrict__ inp,
               const float* __restrict__ Wt,
               const float* __restrict__ bias,
               float* __restrict__ out) {
  __shared__ float rs[8][1024];
  int r0 = blockIdx.x << 3;
#pragma unroll
  for (int l = threadIdx.x; l < 2048; l += 256) {
    int r = l >> 8, f4 = (l & 255) << 2;
    *reinterpret_cast<float4*>(&rs[r][f4]) =
        *reinterpret_cast<const float4*>(&inp[(size_t)(r0 + r) * 1024 + f4]);
  }
  __syncthreads();
  int r = threadIdx.x >> 5;
  int tg = threadIdx.x & 31;
  int tag2 = tg + 32;
  bool has2 = (tag2 < TAGS);
  float a0 = 0.f, a1 = 0.f;
  for (int k = 0; k < 1024; k += 4) {
    float4 xv = *reinterpret_cast<const float4*>(&rs[r][k]);
    float4 w0 = *reinterpret_cast<const float4*>(&Wt[(size_t)tg * 1024 + k]);
    a0 += xv.x * w0.x + xv.y * w0.y + xv.z * w0.z + xv.w * w0.w;
    if (has2) {
      float4 w1 = *reinterpret_cast<const float4*>(&Wt[(size_t)tag2 * 1024 + k]);
      a1 += xv.x * w1.x + xv.y * w1.y + xv.z * w1.z + xv.w * w1.w;
    }
  }
  int row = r0 + r;
  int tq = row >> 6, bb = row & 63;
  size_t obase = ((size_t)bb * T + tq) * TAGS;
  out[obase + tg] = a0 + bias[tg];
  if (has2) out[obase + tag2] = a1 + bias[tag2];
}

// ---------------------------------------------------------------------------
extern "C" void kernel_launch(void* const* d_in, const int* in_sizes, int n_in,
                              void* d_out, int out_size) {
  const int* x = (const int*)d_in[0];
  const float* emb = (const float*)d_in[2];
  const float* Wih_f1 = (const float*)d_in[3];
  const float* Whh_f1 = (const float*)d_in[4];
  const float* bih_f1 = (const float*)d_in[5];
  const float* bhh_f1 = (const float*)d_in[6];
  const float* Wih_b1 = (const float*)d_in[7];
  const float* Whh_b1 = (const float*)d_in[8];
  const float* bih_b1 = (const float*)d_in[9];
  const float* bhh_b1 = (const float*)d_in[10];
  const float* Wih_f2 = (const float*)d_in[11];
  const float* Whh_f2 = (const float*)d_in[12];
  const float* bih_f2 = (const float*)d_in[13];
  const float* bhh_f2 = (const float*)d_in[14];
  const float* Wih_b2 = (const float*)d_in[15];
  const float* Whh_b2 = (const float*)d_in[16];
  const float* bih_b2 = (const float*)d_in[17];
  const float* bhh_b2 = (const float*)d_in[18];
  const float* fcW = (const float*)d_in[19];
  const float* fcb = (const float*)d_in[20];
  float* out = (float*)d_out;

  float *xs, *pre_f, *pre_b, *out1, *out2;
  cudaGetSymbolAddress((void**)&xs, g_xs);
  cudaGetSymbolAddress((void**)&pre_f, g_pre_f);
  cudaGetSymbolAddress((void**)&pre_b, g_pre_b);
  cudaGetSymbolAddress((void**)&out1, g_out1);
  cudaGetSymbolAddress((void**)&out2, g_out2);

  static bool attr_set = false;
  if (!attr_set) {
    cudaFuncSetAttribute(lstm_persistent,
                         cudaFuncAttributeMaxDynamicSharedMemorySize, 65536);
    attr_set = true;
  }

  embed_kernel<<<M, 128>>>(x, emb);

  dim3 gg(G / 128, M / 128);      // (16, 128)

  // Layer 1
  init_layer_kernel<<<(4 * H * B + 255) / 256, 256>>>();
  sgemm_bias_kernel<E><<<gg, 256>>>(xs, Wih_f1, bih_f1, bhh_f1, pre_f);
  sgemm_bias_kernel<E><<<gg, 256>>>(xs, Wih_b1, bih_b1, bhh_b1, pre_b);
  lstm_persistent<<<2 * NBLK_PER_DIR, 256, 65536>>>(pre_f, pre_b,
                                                    Whh_f1, Whh_b1, out1);

  // Layer 2
  init_layer_kernel<<<(4 * H * B + 255) / 256, 256>>>();
  sgemm_bias_kernel<2 * H><<<gg, 256>>>(out1, Wih_f2, bih_f2, bhh_f2, pre_f);
  sgemm_bias_kernel<2 * H><<<gg, 256>>>(out1, Wih_b2, bih_b2, bhh_b2, pre_b);
  lstm_persistent<<<2 * NBLK_PER_DIR, 256, 65536>>>(pre_f, pre_b,
                                                    Whh_f2, Whh_b2, out2);

  fc_kernel<<<M / 8, 256>>>(out2, fcW, fcb, out);
}